// round 13
// baseline (speedup 1.0000x reference)
#include <cuda_runtime.h>
#include <cuda_fp16.h>
#include <cstdint>

#define EMS 1024
#define NH 16
#define HD 64
#define SEQ 2048
#define BATCH 2

// ---------------------------------------------------------------------------
// PTX helpers
// ---------------------------------------------------------------------------
__device__ __forceinline__ uint32_t smem_u32(const void* p) {
    uint32_t a;
    asm("{ .reg .u64 t; cvta.to.shared.u64 t, %1; cvt.u32.u64 %0, t; }" : "=r"(a) : "l"(p));
    return a;
}
#define CP_ASYNC16(dst, src) \
    asm volatile("cp.async.cg.shared.global [%0], [%1], 16;" :: "r"(dst), "l"(src) : "memory")
#define CP_COMMIT() asm volatile("cp.async.commit_group;" ::: "memory")
#define CP_WAIT(n)  asm volatile("cp.async.wait_group %0;" :: "n"(n) : "memory")

__device__ __forceinline__ void ldsm_x4(uint32_t* r, uint32_t addr) {
    asm volatile("ldmatrix.sync.aligned.m8n8.x4.shared.b16 {%0,%1,%2,%3}, [%4];"
        : "=r"(r[0]), "=r"(r[1]), "=r"(r[2]), "=r"(r[3]) : "r"(addr));
}
__device__ __forceinline__ void ldsm_x4_t(uint32_t* r, uint32_t addr) {
    asm volatile("ldmatrix.sync.aligned.m8n8.x4.trans.shared.b16 {%0,%1,%2,%3}, [%4];"
        : "=r"(r[0]), "=r"(r[1]), "=r"(r[2]), "=r"(r[3]) : "r"(addr));
}
__device__ __forceinline__ void mma16816h(float* c, const uint32_t* a, const uint32_t* b) {
    asm volatile("mma.sync.aligned.m16n8k16.row.col.f32.f16.f16.f32 "
        "{%0,%1,%2,%3}, {%4,%5,%6,%7}, {%8,%9}, {%0,%1,%2,%3};"
        : "+f"(c[0]), "+f"(c[1]), "+f"(c[2]), "+f"(c[3])
        : "r"(a[0]), "r"(a[1]), "r"(a[2]), "r"(a[3]), "r"(b[0]), "r"(b[1]));
}
__device__ __forceinline__ uint32_t pack_h2(float lo, float hi) {
    __half2 t = __floats2half2_rn(lo, hi);
    return *(uint32_t*)&t;
}
__device__ __forceinline__ uint32_t h2exp2(uint32_t a) {
    uint32_t r;
    asm("ex2.approx.f16x2 %0, %1;" : "=r"(r) : "r"(a));
    return r;
}

// ---------------------------------------------------------------------------
// Device scratch (fp16)
// ---------------------------------------------------------------------------
__device__ __half g_Q16[BATCH*NH*SEQ*HD];   // pre-scaled by 0.125*log2(e)
__device__ __half g_K16[BATCH*NH*SEQ*HD];
__device__ __half g_V16[BATCH*NH*SEQ*HD];
__device__ __half g_E16[4096 * 1024];
__device__ __half g_X16[4096 * 1024];
__device__ __half g_Wq16[1024 * 1024], g_Wk16[1024 * 1024], g_Wv16[1024 * 1024];

// ---------------------------------------------------------------------------
// fp32 -> fp16 convert, MLP=4
// ---------------------------------------------------------------------------
__global__ __launch_bounds__(256) void convert_kernel(
    const float* __restrict__ embed, const float* __restrict__ qin,
    const float* __restrict__ Wq, const float* __restrict__ Wk, const float* __restrict__ Wv)
{
    const int z = blockIdx.y;
    const float* src; __half* dst; int n4;
    switch (z) {
        case 0: src = embed; dst = g_E16;  n4 = 4096 * 256; break;
        case 1: src = qin;   dst = g_X16;  n4 = 4096 * 256; break;
        case 2: src = Wq;    dst = g_Wq16; n4 = 1024 * 256; break;
        case 3: src = Wk;    dst = g_Wk16; n4 = 1024 * 256; break;
        default: src = Wv;   dst = g_Wv16; n4 = 1024 * 256; break;
    }
    const int base = blockIdx.x * 1024 + threadIdx.x;
    if (base >= n4) return;
    float4 v[4];
    #pragma unroll
    for (int i = 0; i < 4; i++) {
        const int t = base + i * 256;
        if (t < n4) v[i] = ((const float4*)src)[t];
    }
    #pragma unroll
    for (int i = 0; i < 4; i++) {
        const int t = base + i * 256;
        if (t < n4)
            *(uint2*)(dst + (size_t)t * 4) =
                make_uint2(pack_h2(v[i].x, v[i].y), pack_h2(v[i].z, v[i].w));
    }
}

// ---------------------------------------------------------------------------
// fp16 1-pass projection: C = A @ W^T + bias. 128x128 CTA tile.
// 4 warps in 2x2 grid, 64x64 per warp -> B-fragment redundancy 2x (was 4x),
// 24% less smem traffic per chunk. 3-stage cp.async pipeline.
// ---------------------------------------------------------------------------
#define TILE_B 18432            // 128 rows * 144 B
#define BUF_B  (2 * TILE_B)     // A, W
#define PSTAGE 3

__global__ __launch_bounds__(128, 2) void proj_mma_kernel(
    const float* __restrict__ bq, const float* __restrict__ bk, const float* __restrict__ bv)
{
    extern __shared__ char ds[];
    __shared__ float s_bias[128];

    const int tid  = threadIdx.x;
    const int wid  = tid >> 5;
    const int lane = tid & 31;
    const int z  = blockIdx.z;
    const int n0 = blockIdx.x * 128;
    const int m0 = blockIdx.y * 128;

    const __half *A, *W; const float* bias;
    if (z == 0)      { A = g_X16; W = g_Wq16; bias = bq; }
    else if (z == 1) { A = g_E16; W = g_Wk16; bias = bk; }
    else             { A = g_E16; W = g_Wv16; bias = bv; }

    s_bias[tid] = bias[n0 + tid];

    const uint32_t smb = smem_u32(ds);
    const __half* srcs[2] = { A + (size_t)m0 * 1024, W + (size_t)n0 * 1024 };

    const int cprow = tid >> 3;          // 0..15
    const int cpseg = (tid & 7) * 16;

    auto issue = [&](int c) {
        const uint32_t bbase = smb + (c % PSTAGE) * BUF_B;
        const int k0 = c * 64;
        #pragma unroll
        for (int t2 = 0; t2 < 2; t2++) {
            const __half* sp = srcs[t2] + k0;
            const uint32_t tbase = bbase + t2 * TILE_B;
            #pragma unroll
            for (int it = 0; it < 8; it++) {
                const int r = cprow + it * 16;
                CP_ASYNC16(tbase + r * 144 + cpseg,
                           (const void*)((const char*)(sp + (size_t)r * 1024) + cpseg));
            }
        }
        CP_COMMIT();
    };

    const int wm = (wid >> 1) * 64;
    const int wn = (wid & 1) * 64;

    float acc[4][8][4];
    #pragma unroll
    for (int mt = 0; mt < 4; mt++)
        #pragma unroll
        for (int nt = 0; nt < 8; nt++)
            #pragma unroll
            for (int e = 0; e < 4; e++) acc[mt][nt][e] = 0.f;

    const int a_row = lane & 15;
    const int a_kb  = ((lane >> 4) << 3) * 2;
    const int b_row = lane & 7;
    const int b_kb  = (((lane >> 3) & 1) << 3) * 2;
    const int b_nx  = (lane >= 16) ? 8 : 0;

    issue(0);
    issue(1);

    for (int c = 0; c < 16; c++) {
        if (c + 1 < 16) { CP_WAIT(1); } else { CP_WAIT(0); }
        __syncthreads();
        if (c + 2 < 16) issue(c + 2);

        const uint32_t bbase = smb + (c % PSTAGE) * BUF_B;
        const uint32_t Abase = bbase;
        const uint32_t Wbase = bbase + TILE_B;

        #pragma unroll
        for (int ks = 0; ks < 4; ks++) {
            const int kb = ks * 32;
            uint32_t aF[4][4];
            #pragma unroll
            for (int mt = 0; mt < 4; mt++)
                ldsm_x4(aF[mt], Abase + (wm + mt * 16 + a_row) * 144 + kb + a_kb);

            uint32_t bF[8][2];
            #pragma unroll
            for (int p = 0; p < 4; p++) {
                uint32_t r4[4];
                ldsm_x4(r4, Wbase + (wn + p * 16 + b_nx + b_row) * 144 + kb + b_kb);
                bF[2 * p][0] = r4[0];     bF[2 * p][1] = r4[1];
                bF[2 * p + 1][0] = r4[2]; bF[2 * p + 1][1] = r4[3];
            }

            #pragma unroll
            for (int mt = 0; mt < 4; mt++)
                #pragma unroll
                for (int nt = 0; nt < 8; nt++)
                    mma16816h(acc[mt][nt], aF[mt], bF[nt]);
        }
    }

    // Epilogue: bias, (Q) scale into exp2 domain, fp16 pack, [b,h,s,d]
    __half* dst = (z == 0) ? g_Q16 : (z == 1) ? g_K16 : g_V16;
    const float osc = (z == 0) ? 0.125f * 1.44269504f : 1.0f;
    const int rq = lane >> 2;
    const int cq = (lane & 3) * 2;
    #pragma unroll
    for (int mt = 0; mt < 4; mt++) {
        #pragma unroll
        for (int half = 0; half < 2; half++) {
            const int m  = m0 + wm + mt * 16 + rq + half * 8;
            const int bb = m >> 11;
            const int s  = m & (SEQ - 1);
            #pragma unroll
            for (int nt = 0; nt < 8; nt++) {
                const int nl = wn + nt * 8 + cq;
                const int n  = n0 + nl;
                const int h  = n >> 6, dd = n & 63;
                float vx = (acc[mt][nt][half * 2 + 0] + s_bias[nl])     * osc;
                float vy = (acc[mt][nt][half * 2 + 1] + s_bias[nl + 1]) * osc;
                const size_t idx = (((size_t)(bb * NH + h) * SEQ) + s) * HD + dd;
                *(uint32_t*)(dst + idx) = pack_h2(vx, vy);
            }
        }
    }
}

// ---------------------------------------------------------------------------
// Tensor-core flash attention (unchanged from R12 best).
// ---------------------------------------------------------------------------
#define ATILE 9216              // 64 rows * 144B
#define ASTAGE (2 * ATILE)      // K, V
#define NSTAGE 3

__global__ __launch_bounds__(128, 4) void attn_mma_kernel(float* __restrict__ out)
{
    extern __shared__ char ds[];
    const int tid  = threadIdx.x;
    const int w    = tid >> 5;
    const int lane = tid & 31;
    const int gid  = lane >> 2;
    const int tig  = lane & 3;
    const int bh   = blockIdx.y;
    const int q0   = blockIdx.x * 64;

    const size_t base = (size_t)bh * SEQ * HD;
    const uint32_t smb = smem_u32(ds);

    uint32_t qh[4][4];
    {
        const __half* Q = g_Q16 + base;
        const int r0 = q0 + w * 16 + gid;
        #pragma unroll
        for (int kt = 0; kt < 4; kt++) {
            const int c0 = kt * 16 + 2 * tig;
            qh[kt][0] = *(const uint32_t*)(Q + (size_t)r0 * HD + c0);
            qh[kt][1] = *(const uint32_t*)(Q + (size_t)(r0 + 8) * HD + c0);
            qh[kt][2] = *(const uint32_t*)(Q + (size_t)r0 * HD + c0 + 8);
            qh[kt][3] = *(const uint32_t*)(Q + (size_t)(r0 + 8) * HD + c0 + 8);
        }
    }

    const __half* tsrc[2] = { g_K16 + base, g_V16 + base };

    auto issue = [&](int c) {
        const uint32_t sb = smb + (c % NSTAGE) * ASTAGE;
        const int k0 = c * 64;
        #pragma unroll
        for (int i = 0; i < 8; i++) {
            const int ch = tid + i * 128;
            const int t2 = ch >> 9, row = (ch >> 3) & 63, seg = (ch & 7) * 16;
            CP_ASYNC16(sb + t2 * ATILE + row * 144 + seg,
                       (const void*)((const char*)(tsrc[t2] + (size_t)(k0 + row) * HD) + seg));
        }
        CP_COMMIT();
    };

    float m_r[2] = { -1e30f, -1e30f };
    float l_r[2] = { 0.f, 0.f };
    float oacc[8][4];
    #pragma unroll
    for (int j = 0; j < 8; j++)
        #pragma unroll
        for (int e = 0; e < 4; e++) oacc[j][e] = 0.f;

    const int b_row = lane & 7;
    const int b_kb  = ((lane >> 3) & 1) * 16;
    const int b_nx  = (lane & 16) ? 8 : 0;
    const int v_row = lane & 15;
    const int v_cb  = (lane & 16) ? 16 : 0;

    issue(0);
    issue(1);

    for (int c = 0; c < 32; c++) {
        if (c + 1 < 32) { CP_WAIT(1); } else { CP_WAIT(0); }
        __syncthreads();
        if (c + 2 < 32) issue(c + 2);

        const uint32_t Kb = smb + (c % NSTAGE) * ASTAGE;
        const uint32_t Vb = Kb + ATILE;

        float sacc[8][4];
        #pragma unroll
        for (int j = 0; j < 8; j++)
            #pragma unroll
            for (int e = 0; e < 4; e++) sacc[j][e] = 0.f;

        #pragma unroll
        for (int kt = 0; kt < 4; kt++) {
            const int kb = kt * 32;
            uint32_t bK[4][4];
            #pragma unroll
            for (int p = 0; p < 4; p++)
                ldsm_x4(bK[p], Kb + (p * 16 + b_nx + b_row) * 144 + kb + b_kb);
            #pragma unroll
            for (int j = 0; j < 8; j++)
                mma16816h(sacc[j], qh[kt], &bK[j >> 1][(j & 1) * 2]);
        }

        float mx0 = -1e30f, mx1 = -1e30f;
        #pragma unroll
        for (int j = 0; j < 8; j++) {
            mx0 = fmaxf(mx0, fmaxf(sacc[j][0], sacc[j][1]));
            mx1 = fmaxf(mx1, fmaxf(sacc[j][2], sacc[j][3]));
        }
        mx0 = fmaxf(mx0, __shfl_xor_sync(0xffffffffu, mx0, 1));
        mx0 = fmaxf(mx0, __shfl_xor_sync(0xffffffffu, mx0, 2));
        mx1 = fmaxf(mx1, __shfl_xor_sync(0xffffffffu, mx1, 1));
        mx1 = fmaxf(mx1, __shfl_xor_sync(0xffffffffu, mx1, 2));

        const float mn0 = fmaxf(m_r[0], mx0);
        const float mn1 = fmaxf(m_r[1], mx1);
        const float al0 = exp2f(m_r[0] - mn0);
        const float al1 = exp2f(m_r[1] - mn1);
        m_r[0] = mn0; m_r[1] = mn1;

        uint32_t pa[4][4];
        float rs0 = 0.f, rs1 = 0.f;
        #pragma unroll
        for (int j = 0; j < 8; j++) {
            const uint32_t p01 = h2exp2(pack_h2(sacc[j][0] - mn0, sacc[j][1] - mn0));
            const uint32_t p23 = h2exp2(pack_h2(sacc[j][2] - mn1, sacc[j][3] - mn1));
            const int kt2 = j >> 1, rb = (j & 1) * 2;
            pa[kt2][rb + 0] = p01;
            pa[kt2][rb + 1] = p23;
            float2 f01 = __half22float2(*(const __half2*)&p01);
            float2 f23 = __half22float2(*(const __half2*)&p23);
            rs0 += f01.x + f01.y;
            rs1 += f23.x + f23.y;
        }
        rs0 += __shfl_xor_sync(0xffffffffu, rs0, 1);
        rs0 += __shfl_xor_sync(0xffffffffu, rs0, 2);
        rs1 += __shfl_xor_sync(0xffffffffu, rs1, 1);
        rs1 += __shfl_xor_sync(0xffffffffu, rs1, 2);
        l_r[0] = l_r[0] * al0 + rs0;
        l_r[1] = l_r[1] * al1 + rs1;

        #pragma unroll
        for (int j = 0; j < 8; j++) {
            oacc[j][0] *= al0; oacc[j][1] *= al0;
            oacc[j][2] *= al1; oacc[j][3] *= al1;
        }

        #pragma unroll
        for (int kt2 = 0; kt2 < 4; kt2++) {
            uint32_t bV[4][4];
            #pragma unroll
            for (int p = 0; p < 4; p++)
                ldsm_x4_t(bV[p], Vb + (kt2 * 16 + v_row) * 144 + p * 32 + v_cb);
            #pragma unroll
            for (int j = 0; j < 8; j++)
                mma16816h(oacc[j], pa[kt2], &bV[j >> 1][(j & 1) * 2]);
        }
    }

    const int bb = bh >> 4;
    const int h  = bh & 15;
    const float inv0 = 1.f / l_r[0];
    const float inv1 = 1.f / l_r[1];
    const int qr = q0 + w * 16 + gid;
    #pragma unroll
    for (int j = 0; j < 8; j++) {
        const int dd = 8 * j + 2 * tig;
        float2 v0 = make_float2(oacc[j][0] * inv0, oacc[j][1] * inv0);
        float2 v1 = make_float2(oacc[j][2] * inv1, oacc[j][3] * inv1);
        *(float2*)&out[((size_t)(bb * SEQ + qr)) * EMS + h * HD + dd]     = v0;
        *(float2*)&out[((size_t)(bb * SEQ + qr + 8)) * EMS + h * HD + dd] = v1;
    }
}

// ---------------------------------------------------------------------------
extern "C" void kernel_launch(void* const* d_in, const int* in_sizes, int n_in,
                              void* d_out, int out_size)
{
    const float* embed = (const float*)d_in[0];
    const float* q     = (const float*)d_in[1];
    const float* Wk    = (const float*)d_in[2];
    const float* bk    = (const float*)d_in[3];
    const float* Wq    = (const float*)d_in[4];
    const float* bq    = (const float*)d_in[5];
    const float* Wv    = (const float*)d_in[6];
    const float* bv    = (const float*)d_in[7];
    float* out = (float*)d_out;

    convert_kernel<<<dim3(1024, 5), 256>>>(embed, q, Wq, Wk, Wv);

    cudaFuncSetAttribute(proj_mma_kernel, cudaFuncAttributeMaxDynamicSharedMemorySize, PSTAGE * BUF_B);
    proj_mma_kernel<<<dim3(EMS / 128, (BATCH * SEQ) / 128, 3), 128, PSTAGE * BUF_B>>>(bq, bk, bv);

    cudaFuncSetAttribute(attn_mma_kernel, cudaFuncAttributeMaxDynamicSharedMemorySize, NSTAGE * ASTAGE);
    attn_mma_kernel<<<dim3(SEQ / 64, BATCH * NH), 128, NSTAGE * ASTAGE>>>(out);
}

// round 14
// speedup vs baseline: 1.0114x; 1.0114x over previous
#include <cuda_runtime.h>
#include <cuda_fp16.h>
#include <cstdint>

#define EMS 1024
#define NH 16
#define HD 64
#define SEQ 2048
#define BATCH 2

// ---------------------------------------------------------------------------
// PTX helpers
// ---------------------------------------------------------------------------
__device__ __forceinline__ uint32_t smem_u32(const void* p) {
    uint32_t a;
    asm("{ .reg .u64 t; cvta.to.shared.u64 t, %1; cvt.u32.u64 %0, t; }" : "=r"(a) : "l"(p));
    return a;
}
#define CP_ASYNC16(dst, src) \
    asm volatile("cp.async.cg.shared.global [%0], [%1], 16;" :: "r"(dst), "l"(src) : "memory")
#define CP_COMMIT() asm volatile("cp.async.commit_group;" ::: "memory")
#define CP_WAIT(n)  asm volatile("cp.async.wait_group %0;" :: "n"(n) : "memory")

__device__ __forceinline__ void ldsm_x4(uint32_t* r, uint32_t addr) {
    asm volatile("ldmatrix.sync.aligned.m8n8.x4.shared.b16 {%0,%1,%2,%3}, [%4];"
        : "=r"(r[0]), "=r"(r[1]), "=r"(r[2]), "=r"(r[3]) : "r"(addr));
}
__device__ __forceinline__ void ldsm_x4_t(uint32_t* r, uint32_t addr) {
    asm volatile("ldmatrix.sync.aligned.m8n8.x4.trans.shared.b16 {%0,%1,%2,%3}, [%4];"
        : "=r"(r[0]), "=r"(r[1]), "=r"(r[2]), "=r"(r[3]) : "r"(addr));
}
__device__ __forceinline__ void mma16816h(float* c, const uint32_t* a, const uint32_t* b) {
    asm volatile("mma.sync.aligned.m16n8k16.row.col.f32.f16.f16.f32 "
        "{%0,%1,%2,%3}, {%4,%5,%6,%7}, {%8,%9}, {%0,%1,%2,%3};"
        : "+f"(c[0]), "+f"(c[1]), "+f"(c[2]), "+f"(c[3])
        : "r"(a[0]), "r"(a[1]), "r"(a[2]), "r"(a[3]), "r"(b[0]), "r"(b[1]));
}
__device__ __forceinline__ uint32_t pack_h2(float lo, float hi) {
    __half2 t = __floats2half2_rn(lo, hi);
    return *(uint32_t*)&t;
}
__device__ __forceinline__ uint32_t h2exp2(uint32_t a) {
    uint32_t r;
    asm("ex2.approx.f16x2 %0, %1;" : "=r"(r) : "r"(a));
    return r;
}

// ---------------------------------------------------------------------------
// Device scratch (fp16)
// ---------------------------------------------------------------------------
__device__ __half g_Q16[BATCH*NH*SEQ*HD];   // pre-scaled by 0.125*log2(e)
__device__ __half g_K16[BATCH*NH*SEQ*HD];
__device__ __half g_V16[BATCH*NH*SEQ*HD];
__device__ __half g_E16[4096 * 1024];
__device__ __half g_X16[4096 * 1024];
__device__ __half g_Wq16[1024 * 1024], g_Wk16[1024 * 1024], g_Wv16[1024 * 1024];

// ---------------------------------------------------------------------------
// fp32 -> fp16 convert, MLP=8 (8 independent float4 loads in flight)
// ---------------------------------------------------------------------------
__global__ __launch_bounds__(256) void convert_kernel(
    const float* __restrict__ embed, const float* __restrict__ qin,
    const float* __restrict__ Wq, const float* __restrict__ Wk, const float* __restrict__ Wv)
{
    const int z = blockIdx.y;
    const float* src; __half* dst; int n4;
    switch (z) {
        case 0: src = embed; dst = g_E16;  n4 = 4096 * 256; break;
        case 1: src = qin;   dst = g_X16;  n4 = 4096 * 256; break;
        case 2: src = Wq;    dst = g_Wq16; n4 = 1024 * 256; break;
        case 3: src = Wk;    dst = g_Wk16; n4 = 1024 * 256; break;
        default: src = Wv;   dst = g_Wv16; n4 = 1024 * 256; break;
    }
    const int base = blockIdx.x * 2048 + threadIdx.x;
    if (base >= n4) return;
    float4 v[8];
    #pragma unroll
    for (int i = 0; i < 8; i++) {
        const int t = base + i * 256;
        if (t < n4) v[i] = ((const float4*)src)[t];
    }
    #pragma unroll
    for (int i = 0; i < 8; i++) {
        const int t = base + i * 256;
        if (t < n4)
            *(uint2*)(dst + (size_t)t * 4) =
                make_uint2(pack_h2(v[i].x, v[i].y), pack_h2(v[i].z, v[i].w));
    }
}

// ---------------------------------------------------------------------------
// fp16 1-pass projection (R12 configuration): 128x128 CTA tile, 8 warps 4x2.
// 3-stage cp.async pipeline.
// ---------------------------------------------------------------------------
#define TILE_B 18432            // 128 rows * 144 B
#define BUF_B  (2 * TILE_B)     // A, W
#define PSTAGE 3

__global__ __launch_bounds__(256, 2) void proj_mma_kernel(
    const float* __restrict__ bq, const float* __restrict__ bk, const float* __restrict__ bv)
{
    extern __shared__ char ds[];
    __shared__ float s_bias[128];

    const int tid  = threadIdx.x;
    const int wid  = tid >> 5;
    const int lane = tid & 31;
    const int z  = blockIdx.z;
    const int n0 = blockIdx.x * 128;
    const int m0 = blockIdx.y * 128;

    const __half *A, *W; const float* bias;
    if (z == 0)      { A = g_X16; W = g_Wq16; bias = bq; }
    else if (z == 1) { A = g_E16; W = g_Wk16; bias = bk; }
    else             { A = g_E16; W = g_Wv16; bias = bv; }

    if (tid < 128) s_bias[tid] = bias[n0 + tid];

    const uint32_t smb = smem_u32(ds);
    const __half* srcs[2] = { A + (size_t)m0 * 1024, W + (size_t)n0 * 1024 };

    const int cprow = tid >> 3;
    const int cpseg = (tid & 7) * 16;

    auto issue = [&](int c) {
        const uint32_t bbase = smb + (c % PSTAGE) * BUF_B;
        const int k0 = c * 64;
        #pragma unroll
        for (int t2 = 0; t2 < 2; t2++) {
            const __half* sp = srcs[t2] + k0;
            const uint32_t tbase = bbase + t2 * TILE_B;
            #pragma unroll
            for (int it = 0; it < 4; it++) {
                const int r = cprow + it * 32;
                CP_ASYNC16(tbase + r * 144 + cpseg,
                           (const void*)((const char*)(sp + (size_t)r * 1024) + cpseg));
            }
        }
        CP_COMMIT();
    };

    const int wm = (wid >> 1) * 32;
    const int wn = (wid & 1) * 64;

    float acc[2][8][4];
    #pragma unroll
    for (int mt = 0; mt < 2; mt++)
        #pragma unroll
        for (int nt = 0; nt < 8; nt++)
            #pragma unroll
            for (int e = 0; e < 4; e++) acc[mt][nt][e] = 0.f;

    const int a_row = lane & 15;
    const int a_kb  = ((lane >> 4) << 3) * 2;
    const int b_row = lane & 7;
    const int b_kb  = (((lane >> 3) & 1) << 3) * 2;
    const int b_nx  = (lane >= 16) ? 8 : 0;

    issue(0);
    issue(1);

    for (int c = 0; c < 16; c++) {
        if (c + 1 < 16) { CP_WAIT(1); } else { CP_WAIT(0); }
        __syncthreads();
        if (c + 2 < 16) issue(c + 2);

        const uint32_t bbase = smb + (c % PSTAGE) * BUF_B;
        const uint32_t Abase = bbase;
        const uint32_t Wbase = bbase + TILE_B;

        #pragma unroll
        for (int ks = 0; ks < 4; ks++) {
            const int kb = ks * 32;
            uint32_t aF[2][4];
            #pragma unroll
            for (int mt = 0; mt < 2; mt++)
                ldsm_x4(aF[mt], Abase + (wm + mt * 16 + a_row) * 144 + kb + a_kb);

            uint32_t bF[8][2];
            #pragma unroll
            for (int p = 0; p < 4; p++) {
                uint32_t r4[4];
                ldsm_x4(r4, Wbase + (wn + p * 16 + b_nx + b_row) * 144 + kb + b_kb);
                bF[2 * p][0] = r4[0];     bF[2 * p][1] = r4[1];
                bF[2 * p + 1][0] = r4[2]; bF[2 * p + 1][1] = r4[3];
            }

            #pragma unroll
            for (int mt = 0; mt < 2; mt++)
                #pragma unroll
                for (int nt = 0; nt < 8; nt++)
                    mma16816h(acc[mt][nt], aF[mt], bF[nt]);
        }
    }

    // Epilogue: bias, (Q) scale into exp2 domain, fp16 pack, [b,h,s,d]
    __half* dst = (z == 0) ? g_Q16 : (z == 1) ? g_K16 : g_V16;
    const float osc = (z == 0) ? 0.125f * 1.44269504f : 1.0f;
    const int rq = lane >> 2;
    const int cq = (lane & 3) * 2;
    #pragma unroll
    for (int mt = 0; mt < 2; mt++) {
        #pragma unroll
        for (int half = 0; half < 2; half++) {
            const int m  = m0 + wm + mt * 16 + rq + half * 8;
            const int bb = m >> 11;
            const int s  = m & (SEQ - 1);
            #pragma unroll
            for (int nt = 0; nt < 8; nt++) {
                const int nl = wn + nt * 8 + cq;
                const int n  = n0 + nl;
                const int h  = n >> 6, dd = n & 63;
                float vx = (acc[mt][nt][half * 2 + 0] + s_bias[nl])     * osc;
                float vy = (acc[mt][nt][half * 2 + 1] + s_bias[nl + 1]) * osc;
                const size_t idx = (((size_t)(bb * NH + h) * SEQ) + s) * HD + dd;
                *(uint32_t*)(dst + idx) = pack_h2(vx, vy);
            }
        }
    }
}

// ---------------------------------------------------------------------------
// Tensor-core flash attention (R12 best, unchanged).
// ---------------------------------------------------------------------------
#define ATILE 9216              // 64 rows * 144B
#define ASTAGE (2 * ATILE)      // K, V
#define NSTAGE 3

__global__ __launch_bounds__(128, 4) void attn_mma_kernel(float* __restrict__ out)
{
    extern __shared__ char ds[];
    const int tid  = threadIdx.x;
    const int w    = tid >> 5;
    const int lane = tid & 31;
    const int gid  = lane >> 2;
    const int tig  = lane & 3;
    const int bh   = blockIdx.y;
    const int q0   = blockIdx.x * 64;

    const size_t base = (size_t)bh * SEQ * HD;
    const uint32_t smb = smem_u32(ds);

    uint32_t qh[4][4];
    {
        const __half* Q = g_Q16 + base;
        const int r0 = q0 + w * 16 + gid;
        #pragma unroll
        for (int kt = 0; kt < 4; kt++) {
            const int c0 = kt * 16 + 2 * tig;
            qh[kt][0] = *(const uint32_t*)(Q + (size_t)r0 * HD + c0);
            qh[kt][1] = *(const uint32_t*)(Q + (size_t)(r0 + 8) * HD + c0);
            qh[kt][2] = *(const uint32_t*)(Q + (size_t)r0 * HD + c0 + 8);
            qh[kt][3] = *(const uint32_t*)(Q + (size_t)(r0 + 8) * HD + c0 + 8);
        }
    }

    const __half* tsrc[2] = { g_K16 + base, g_V16 + base };

    auto issue = [&](int c) {
        const uint32_t sb = smb + (c % NSTAGE) * ASTAGE;
        const int k0 = c * 64;
        #pragma unroll
        for (int i = 0; i < 8; i++) {
            const int ch = tid + i * 128;
            const int t2 = ch >> 9, row = (ch >> 3) & 63, seg = (ch & 7) * 16;
            CP_ASYNC16(sb + t2 * ATILE + row * 144 + seg,
                       (const void*)((const char*)(tsrc[t2] + (size_t)(k0 + row) * HD) + seg));
        }
        CP_COMMIT();
    };

    float m_r[2] = { -1e30f, -1e30f };
    float l_r[2] = { 0.f, 0.f };
    float oacc[8][4];
    #pragma unroll
    for (int j = 0; j < 8; j++)
        #pragma unroll
        for (int e = 0; e < 4; e++) oacc[j][e] = 0.f;

    const int b_row = lane & 7;
    const int b_kb  = ((lane >> 3) & 1) * 16;
    const int b_nx  = (lane & 16) ? 8 : 0;
    const int v_row = lane & 15;
    const int v_cb  = (lane & 16) ? 16 : 0;

    issue(0);
    issue(1);

    for (int c = 0; c < 32; c++) {
        if (c + 1 < 32) { CP_WAIT(1); } else { CP_WAIT(0); }
        __syncthreads();
        if (c + 2 < 32) issue(c + 2);

        const uint32_t Kb = smb + (c % NSTAGE) * ASTAGE;
        const uint32_t Vb = Kb + ATILE;

        float sacc[8][4];
        #pragma unroll
        for (int j = 0; j < 8; j++)
            #pragma unroll
            for (int e = 0; e < 4; e++) sacc[j][e] = 0.f;

        #pragma unroll
        for (int kt = 0; kt < 4; kt++) {
            const int kb = kt * 32;
            uint32_t bK[4][4];
            #pragma unroll
            for (int p = 0; p < 4; p++)
                ldsm_x4(bK[p], Kb + (p * 16 + b_nx + b_row) * 144 + kb + b_kb);
            #pragma unroll
            for (int j = 0; j < 8; j++)
                mma16816h(sacc[j], qh[kt], &bK[j >> 1][(j & 1) * 2]);
        }

        float mx0 = -1e30f, mx1 = -1e30f;
        #pragma unroll
        for (int j = 0; j < 8; j++) {
            mx0 = fmaxf(mx0, fmaxf(sacc[j][0], sacc[j][1]));
            mx1 = fmaxf(mx1, fmaxf(sacc[j][2], sacc[j][3]));
        }
        mx0 = fmaxf(mx0, __shfl_xor_sync(0xffffffffu, mx0, 1));
        mx0 = fmaxf(mx0, __shfl_xor_sync(0xffffffffu, mx0, 2));
        mx1 = fmaxf(mx1, __shfl_xor_sync(0xffffffffu, mx1, 1));
        mx1 = fmaxf(mx1, __shfl_xor_sync(0xffffffffu, mx1, 2));

        const float mn0 = fmaxf(m_r[0], mx0);
        const float mn1 = fmaxf(m_r[1], mx1);
        const float al0 = exp2f(m_r[0] - mn0);
        const float al1 = exp2f(m_r[1] - mn1);
        m_r[0] = mn0; m_r[1] = mn1;

        uint32_t pa[4][4];
        float rs0 = 0.f, rs1 = 0.f;
        #pragma unroll
        for (int j = 0; j < 8; j++) {
            const uint32_t p01 = h2exp2(pack_h2(sacc[j][0] - mn0, sacc[j][1] - mn0));
            const uint32_t p23 = h2exp2(pack_h2(sacc[j][2] - mn1, sacc[j][3] - mn1));
            const int kt2 = j >> 1, rb = (j & 1) * 2;
            pa[kt2][rb + 0] = p01;
            pa[kt2][rb + 1] = p23;
            float2 f01 = __half22float2(*(const __half2*)&p01);
            float2 f23 = __half22float2(*(const __half2*)&p23);
            rs0 += f01.x + f01.y;
            rs1 += f23.x + f23.y;
        }
        rs0 += __shfl_xor_sync(0xffffffffu, rs0, 1);
        rs0 += __shfl_xor_sync(0xffffffffu, rs0, 2);
        rs1 += __shfl_xor_sync(0xffffffffu, rs1, 1);
        rs1 += __shfl_xor_sync(0xffffffffu, rs1, 2);
        l_r[0] = l_r[0] * al0 + rs0;
        l_r[1] = l_r[1] * al1 + rs1;

        #pragma unroll
        for (int j = 0; j < 8; j++) {
            oacc[j][0] *= al0; oacc[j][1] *= al0;
            oacc[j][2] *= al1; oacc[j][3] *= al1;
        }

        #pragma unroll
        for (int kt2 = 0; kt2 < 4; kt2++) {
            uint32_t bV[4][4];
            #pragma unroll
            for (int p = 0; p < 4; p++)
                ldsm_x4_t(bV[p], Vb + (kt2 * 16 + v_row) * 144 + p * 32 + v_cb);
            #pragma unroll
            for (int j = 0; j < 8; j++)
                mma16816h(oacc[j], pa[kt2], &bV[j >> 1][(j & 1) * 2]);
        }
    }

    const int bb = bh >> 4;
    const int h  = bh & 15;
    const float inv0 = 1.f / l_r[0];
    const float inv1 = 1.f / l_r[1];
    const int qr = q0 + w * 16 + gid;
    #pragma unroll
    for (int j = 0; j < 8; j++) {
        const int dd = 8 * j + 2 * tig;
        float2 v0 = make_float2(oacc[j][0] * inv0, oacc[j][1] * inv0);
        float2 v1 = make_float2(oacc[j][2] * inv1, oacc[j][3] * inv1);
        *(float2*)&out[((size_t)(bb * SEQ + qr)) * EMS + h * HD + dd]     = v0;
        *(float2*)&out[((size_t)(bb * SEQ + qr + 8)) * EMS + h * HD + dd] = v1;
    }
}

// ---------------------------------------------------------------------------
extern "C" void kernel_launch(void* const* d_in, const int* in_sizes, int n_in,
                              void* d_out, int out_size)
{
    const float* embed = (const float*)d_in[0];
    const float* q     = (const float*)d_in[1];
    const float* Wk    = (const float*)d_in[2];
    const float* bk    = (const float*)d_in[3];
    const float* Wq    = (const float*)d_in[4];
    const float* bq    = (const float*)d_in[5];
    const float* Wv    = (const float*)d_in[6];
    const float* bv    = (const float*)d_in[7];
    float* out = (float*)d_out;

    convert_kernel<<<dim3(512, 5), 256>>>(embed, q, Wq, Wk, Wv);

    cudaFuncSetAttribute(proj_mma_kernel, cudaFuncAttributeMaxDynamicSharedMemorySize, PSTAGE * BUF_B);
    proj_mma_kernel<<<dim3(EMS / 128, (BATCH * SEQ) / 128, 3), 256, PSTAGE * BUF_B>>>(bq, bk, bv);

    cudaFuncSetAttribute(attn_mma_kernel, cudaFuncAttributeMaxDynamicSharedMemorySize, NSTAGE * ASTAGE);
    attn_mma_kernel<<<dim3(SEQ / 64, BATCH * NH), 128, NSTAGE * ASTAGE>>>(out);
}